// round 8
// baseline (speedup 1.0000x reference)
#include <cuda_runtime.h>
#include <cuda_fp16.h>
#include <cstdint>
#include <cstddef>

// Problem constants
#define BATCH   32768
#define PP      24
#define CIN     64
#define COUT    64
#define NORB    24
#define KK      1536          // P*CIN  (GEMM K)
#define NNDIM   1536          // P*COUT (GEMM N)
#define BK      64            // halfs per k-tile (128 B rows)
#define NKT     (KK / BK)     // 24
#define STAGES  3
#define A_BYTES 16384         // 128 rows x 128B
#define B_BYTES 32768         // 256 rows x 128B
#define STAGE_BYTES (A_BYTES + B_BYTES)      // 48KB
#define SMEM_DYN (STAGES * STAGE_BYTES)      // 144KB

// fp16 operands (device-global scratch; no allocations allowed)
__device__ __half g_Xh[(size_t)BATCH * KK];          // x in fp16, row-major [m][k]
__device__ __half g_KTh[(size_t)NNDIM * KK];         // gathered kernel, [n][k]

// ---------------- helpers ----------------
__device__ __forceinline__ uint32_t smem_u32(const void* p) {
    uint32_t a;
    asm("{ .reg .u64 t; cvta.to.shared.u64 t, %1; cvt.u32.u64 %0, t; }"
        : "=r"(a) : "l"(p));
    return a;
}

#define LDSM4(r, addr) \
    asm volatile("ldmatrix.sync.aligned.m8n8.x4.shared.b16 {%0,%1,%2,%3}, [%4];" \
                 : "=r"((r)[0]), "=r"((r)[1]), "=r"((r)[2]), "=r"((r)[3]) \
                 : "r"(addr))

#define MMA_F16(c, a, b0, b1) \
    asm volatile("mma.sync.aligned.m16n8k16.row.col.f32.f16.f16.f32 " \
                 "{%0,%1,%2,%3}, {%4,%5,%6,%7}, {%8,%9}, {%0,%1,%2,%3};" \
                 : "+f"((c)[0]), "+f"((c)[1]), "+f"((c)[2]), "+f"((c)[3]) \
                 : "r"((a)[0]), "r"((a)[1]), "r"((a)[2]), "r"((a)[3]), \
                   "r"(b0), "r"(b1))

// ---------------- kernel 1: gather KT (fp16) with inline dtype detect ----------
// pair_orbit dtype ambiguity (int32 vs int64): if int64 with values < 24,
// every odd 32-bit word is 0; 288 random int32 values in [0,24) are ~never
// all zero in those positions.
__global__ __launch_bounds__(256) void build_kt(const float* __restrict__ w,
                                                const void* __restrict__ po) {
    __shared__ int is64_sh;
    {
        const uint32_t* pr = (const uint32_t*)po;
        if (threadIdx.x == 0) is64_sh = 1;
        __syncthreads();
        int t = threadIdx.x;
        if (t < 288 && pr[2 * t + 1] != 0u) atomicAnd(&is64_sh, 0);
        __syncthreads();
    }
    const int is64 = is64_sh;

    int idx = blockIdx.x * 256 + threadIdx.x;          // 0 .. NN*KK/8-1
    int n = idx / (KK / 8);
    int k0 = (idx - n * (KK / 8)) * 8;
    int i = n >> 6, o = n & 63;
    int j = k0 >> 6;
    int c0 = k0 & 63;
    int orb;
    if (is64) orb = (int)((const long long*)po)[i * PP + j];
    else      orb = ((const int*)po)[i * PP + j];
    orb = (orb < 0) ? 0 : (orb >= NORB ? NORB - 1 : orb);
    const float* wp = w + o * (CIN * NORB) + c0 * NORB + orb;
    __half2 h[4];
#pragma unroll
    for (int q = 0; q < 4; q++)
        h[q] = __floats2half2_rn(wp[(2 * q) * NORB], wp[(2 * q + 1) * NORB]);
    *reinterpret_cast<uint4*>(&g_KTh[(size_t)n * KK + k0]) =
        *reinterpret_cast<uint4*>(h);
}

// ---------------- kernel 2: convert x -> fp16 ----------------
__global__ __launch_bounds__(256) void convert_x(const float* __restrict__ x) {
    size_t idx = (size_t)blockIdx.x * 256 + threadIdx.x;   // one 8-float chunk
    const float4 f0 = *reinterpret_cast<const float4*>(x + idx * 8);
    const float4 f1 = *reinterpret_cast<const float4*>(x + idx * 8 + 4);
    __half2 h[4];
    h[0] = __floats2half2_rn(f0.x, f0.y);
    h[1] = __floats2half2_rn(f0.z, f0.w);
    h[2] = __floats2half2_rn(f1.x, f1.y);
    h[3] = __floats2half2_rn(f1.z, f1.w);
    *reinterpret_cast<uint4*>(&g_Xh[idx * 8]) = *reinterpret_cast<uint4*>(h);
}

// ---------------- stage loader ----------------
// A tile: 128 rows x 64 halfs (128B rows), swizzle (16B chunk ch ^= row&7)
// B tile: 256 rows x 64 halfs at +A_BYTES
__device__ __forceinline__ void load_stage(uint32_t sb, int slot, int kt,
                                           const __half* __restrict__ xa,
                                           const __half* __restrict__ xb, int tid) {
    const uint32_t base = sb + (uint32_t)slot * STAGE_BYTES;
    const __half* xs = xa + kt * BK;
    const __half* bs = xb + kt * BK;
#pragma unroll
    for (int it = 0; it < 4; it++) {                  // A: 1024 16B chunks
        int idx = tid + it * 256;
        int row = idx >> 3, ch = idx & 7;
        uint32_t dst = base + (uint32_t)(row * 128) + (uint32_t)((ch ^ (row & 7)) << 4);
        const __half* src = xs + (size_t)row * KK + ch * 8;
        asm volatile("cp.async.cg.shared.global [%0], [%1], 16;" :: "r"(dst), "l"(src));
    }
#pragma unroll
    for (int it = 0; it < 8; it++) {                  // B: 2048 16B chunks
        int idx = tid + it * 256;
        int row = idx >> 3, ch = idx & 7;
        uint32_t dst = base + (uint32_t)A_BYTES + (uint32_t)(row * 128)
                     + (uint32_t)((ch ^ (row & 7)) << 4);
        const __half* src = bs + (size_t)row * KK + ch * 8;
        asm volatile("cp.async.cg.shared.global [%0], [%1], 16;" :: "r"(dst), "l"(src));
    }
    asm volatile("cp.async.commit_group;" ::: "memory");
}

// ---------------- kernel 3: fp16 mma.sync GEMM (f32 acc), 64x64 warp tile -----
// out[m, n] = sum_k Xh[m,k] * KTh[n,k] + bias[n % 64]
// CTA tile 128(m) x 256(n); 8 warps in 2(m) x 4(n); warp tile 64 x 64.
__global__ __launch_bounds__(256, 1)
void gemm_f16(const float* __restrict__ bias, float* __restrict__ out) {
    extern __shared__ char smem[];
    __shared__ float bias_sh[64];

    const int tid = threadIdx.x;
    const int wid = tid >> 5, lid = tid & 31;
    const int n_base = blockIdx.x * 256;
    const int m_base = blockIdx.y * 128;

    const uint32_t sb = smem_u32(smem);
    if (tid < 64) bias_sh[tid] = bias[tid];

    // warp layout: 2 (m) x 4 (n); warp tile 64 x 64
    const int wm = (wid & 1) * 64;
    const int wn = (wid >> 1) * 64;
    const int l15 = lid & 15;
    const int lhalf = lid >> 4;

    uint32_t aoff[4]; int ars[4];
#pragma unroll
    for (int mi = 0; mi < 4; mi++) {
        int ar = wm + mi * 16 + l15;
        aoff[mi] = (uint32_t)(ar * 128);
        ars[mi] = ar & 7;
    }
    uint32_t boff[4]; int brs[4];
#pragma unroll
    for (int p = 0; p < 4; p++) {
        int br = wn + p * 16 + l15;
        boff[p] = (uint32_t)(br * 128);
        brs[p] = br & 7;
    }

    float acc[4][8][4];
#pragma unroll
    for (int mi = 0; mi < 4; mi++)
#pragma unroll
        for (int ni = 0; ni < 8; ni++)
#pragma unroll
            for (int q = 0; q < 4; q++) acc[mi][ni][q] = 0.0f;

    const __half* xa = g_Xh + (size_t)m_base * KK;
    const __half* xb = g_KTh + (size_t)n_base * KK;

    load_stage(sb, 0, 0, xa, xb, tid);
    load_stage(sb, 1, 1, xa, xb, tid);

    for (int kt = 0; kt < NKT; kt++) {
        if (kt == NKT - 1) {
            asm volatile("cp.async.wait_group 0;" ::: "memory");
        } else {
            asm volatile("cp.async.wait_group 1;" ::: "memory");
        }
        __syncthreads();
        if (kt + 2 < NKT) {
            int slot = kt + 2;
            slot = slot - (slot / STAGES) * STAGES;
            load_stage(sb, slot, kt + 2, xa, xb, tid);
        }
        {
            int cs = kt - (kt / STAGES) * STAGES;
            const uint32_t baseA = sb + (uint32_t)cs * STAGE_BYTES;
            const uint32_t baseB = baseA + (uint32_t)A_BYTES;
#pragma unroll
            for (int ks = 0; ks < 4; ks++) {          // 4 x k16 per BK=64
                uint32_t a[4][4], b[4][4];
                const int ch = ks * 2 + lhalf;        // 16B chunk within row
#pragma unroll
                for (int mi = 0; mi < 4; mi++)
                    LDSM4(a[mi], baseA + aoff[mi] + (uint32_t)((ch ^ ars[mi]) << 4));
#pragma unroll
                for (int p = 0; p < 4; p++)
                    LDSM4(b[p], baseB + boff[p] + (uint32_t)((ch ^ brs[p]) << 4));
#pragma unroll
                for (int mi = 0; mi < 4; mi++) {
#pragma unroll
                    for (int ni = 0; ni < 8; ni++) {
                        const int p = ni >> 1, t = ni & 1;
                        MMA_F16(acc[mi][ni], a[mi], b[p][t], b[p][t + 2]);
                    }
                }
            }
        }
    }

    // epilogue: coalesced float2 stores + bias
    const int r4 = lid >> 2;
    const int c2 = (lid & 3) * 2;
    float* obase = out + (size_t)m_base * NNDIM + n_base;
#pragma unroll
    for (int mi = 0; mi < 4; mi++) {
#pragma unroll
        for (int ni = 0; ni < 8; ni++) {
            const int row = wm + mi * 16 + r4;
            const int col = wn + ni * 8 + c2;
            const float bx = bias_sh[col & 63];
            const float by = bias_sh[(col + 1) & 63];
            float2 v0, v1;
            v0.x = acc[mi][ni][0] + bx;
            v0.y = acc[mi][ni][1] + by;
            v1.x = acc[mi][ni][2] + bx;
            v1.y = acc[mi][ni][3] + by;
            *reinterpret_cast<float2*>(obase + (size_t)row * NNDIM + col) = v0;
            *reinterpret_cast<float2*>(obase + (size_t)(row + 8) * NNDIM + col) = v1;
        }
    }
}

// ---------------- launch ----------------
extern "C" void kernel_launch(void* const* d_in, const int* in_sizes, int n_in,
                              void* d_out, int out_size) {
    const float* x = nullptr;
    const float* w = nullptr;
    const float* bias = nullptr;
    const void* po = nullptr;
    for (int t = 0; t < n_in; t++) {
        switch (in_sizes[t]) {
            case BATCH * PP * CIN:   x    = (const float*)d_in[t]; break;
            case COUT * CIN * NORB:  w    = (const float*)d_in[t]; break;
            case COUT:               bias = (const float*)d_in[t]; break;
            case PP * PP:            po   = d_in[t];               break;
            default: break;
        }
    }
    float* out = (float*)d_out;

    build_kt<<<(NNDIM * KK / 8) / 256, 256>>>(w, po);
    convert_x<<<(int)(((size_t)BATCH * KK / 8) / 256), 256>>>(x);

    cudaFuncSetAttribute(gemm_f16, cudaFuncAttributeMaxDynamicSharedMemorySize, SMEM_DYN);
    gemm_f16<<<dim3(NNDIM / 256, BATCH / 128), 256, SMEM_DYN>>>(bias, out);
}

// round 10
// speedup vs baseline: 1.0946x; 1.0946x over previous
#include <cuda_runtime.h>
#include <cuda_fp16.h>
#include <cstdint>
#include <cstddef>

// Problem constants
#define BATCH   32768
#define PP      24
#define CIN     64
#define COUT    64
#define NORB    24
#define KK      1536          // P*CIN  (GEMM K)
#define NNDIM   1536          // P*COUT (GEMM N)
#define BK      64            // halfs per k-tile (128 B rows)
#define NKT     (KK / BK)     // 24
#define STAGES  3
#define A_BYTES 16384         // 128 rows x 128B
#define B_BYTES 16384         // 128 rows x 128B
#define STAGE_BYTES (A_BYTES + B_BYTES)      // 32KB
#define SMEM_DYN (STAGES * STAGE_BYTES)      // 96KB per CTA, 2 CTAs/SM

// fp16 operands (device-global scratch; no allocations allowed)
__device__ __half g_Xh[(size_t)BATCH * KK];          // x in fp16, row-major [m][k]
__device__ __half g_KTh[(size_t)NNDIM * KK];         // gathered kernel, [n][k]

// ---------------- helpers ----------------
__device__ __forceinline__ uint32_t smem_u32(const void* p) {
    uint32_t a;
    asm("{ .reg .u64 t; cvta.to.shared.u64 t, %1; cvt.u32.u64 %0, t; }"
        : "=r"(a) : "l"(p));
    return a;
}

#define LDSM4(r, addr) \
    asm volatile("ldmatrix.sync.aligned.m8n8.x4.shared.b16 {%0,%1,%2,%3}, [%4];" \
                 : "=r"((r)[0]), "=r"((r)[1]), "=r"((r)[2]), "=r"((r)[3]) \
                 : "r"(addr))

#define MMA_F16(c, a, b0, b1) \
    asm volatile("mma.sync.aligned.m16n8k16.row.col.f32.f16.f16.f32 " \
                 "{%0,%1,%2,%3}, {%4,%5,%6,%7}, {%8,%9}, {%0,%1,%2,%3};" \
                 : "+f"((c)[0]), "+f"((c)[1]), "+f"((c)[2]), "+f"((c)[3]) \
                 : "r"((a)[0]), "r"((a)[1]), "r"((a)[2]), "r"((a)[3]), \
                   "r"(b0), "r"(b1))

// ---------------- kernel 1: gather KT (fp16) with inline dtype detect ----------
// pair_orbit dtype ambiguity (int32 vs int64): if int64 with values < 24,
// every odd 32-bit word is 0; 288 random int32 values in [0,24) are ~never
// all zero in those positions.
__global__ __launch_bounds__(256) void build_kt(const float* __restrict__ w,
                                                const void* __restrict__ po) {
    __shared__ int is64_sh;
    {
        const uint32_t* pr = (const uint32_t*)po;
        if (threadIdx.x == 0) is64_sh = 1;
        __syncthreads();
        int t = threadIdx.x;
        if (t < 288 && pr[2 * t + 1] != 0u) atomicAnd(&is64_sh, 0);
        __syncthreads();
    }
    const int is64 = is64_sh;

    int idx = blockIdx.x * 256 + threadIdx.x;          // 0 .. NN*KK/8-1
    int n = idx / (KK / 8);
    int k0 = (idx - n * (KK / 8)) * 8;
    int i = n >> 6, o = n & 63;
    int j = k0 >> 6;
    int c0 = k0 & 63;
    int orb;
    if (is64) orb = (int)((const long long*)po)[i * PP + j];
    else      orb = ((const int*)po)[i * PP + j];
    orb = (orb < 0) ? 0 : (orb >= NORB ? NORB - 1 : orb);
    const float* wp = w + o * (CIN * NORB) + c0 * NORB + orb;
    __half2 h[4];
#pragma unroll
    for (int q = 0; q < 4; q++)
        h[q] = __floats2half2_rn(wp[(2 * q) * NORB], wp[(2 * q + 1) * NORB]);
    *reinterpret_cast<uint4*>(&g_KTh[(size_t)n * KK + k0]) =
        *reinterpret_cast<uint4*>(h);
}

// ---------------- kernel 2: convert x -> fp16 ----------------
__global__ __launch_bounds__(256) void convert_x(const float* __restrict__ x) {
    size_t idx = (size_t)blockIdx.x * 256 + threadIdx.x;   // one 8-float chunk
    const float4 f0 = *reinterpret_cast<const float4*>(x + idx * 8);
    const float4 f1 = *reinterpret_cast<const float4*>(x + idx * 8 + 4);
    __half2 h[4];
    h[0] = __floats2half2_rn(f0.x, f0.y);
    h[1] = __floats2half2_rn(f0.z, f0.w);
    h[2] = __floats2half2_rn(f1.x, f1.y);
    h[3] = __floats2half2_rn(f1.z, f1.w);
    *reinterpret_cast<uint4*>(&g_Xh[idx * 8]) = *reinterpret_cast<uint4*>(h);
}

// ---------------- stage loader (128 threads) ----------------
// A tile: 128 rows x 64 halfs (128B rows), swizzle (16B chunk ch ^= row&7)
// B tile: 128 rows x 64 halfs at +A_BYTES
__device__ __forceinline__ void load_stage(uint32_t sb, int slot, int kt,
                                           const __half* __restrict__ xa,
                                           const __half* __restrict__ xb, int tid) {
    const uint32_t base = sb + (uint32_t)slot * STAGE_BYTES;
    const __half* xs = xa + kt * BK;
    const __half* bs = xb + kt * BK;
#pragma unroll
    for (int it = 0; it < 8; it++) {                  // A: 1024 16B chunks
        int idx = tid + it * 128;
        int row = idx >> 3, ch = idx & 7;
        uint32_t dst = base + (uint32_t)(row * 128) + (uint32_t)((ch ^ (row & 7)) << 4);
        const __half* src = xs + (size_t)row * KK + ch * 8;
        asm volatile("cp.async.cg.shared.global [%0], [%1], 16;" :: "r"(dst), "l"(src));
    }
#pragma unroll
    for (int it = 0; it < 8; it++) {                  // B: 1024 16B chunks
        int idx = tid + it * 128;
        int row = idx >> 3, ch = idx & 7;
        uint32_t dst = base + (uint32_t)A_BYTES + (uint32_t)(row * 128)
                     + (uint32_t)((ch ^ (row & 7)) << 4);
        const __half* src = bs + (size_t)row * KK + ch * 8;
        asm volatile("cp.async.cg.shared.global [%0], [%1], 16;" :: "r"(dst), "l"(src));
    }
    asm volatile("cp.async.commit_group;" ::: "memory");
}

// ---------------- kernel 3: fp16 mma.sync GEMM (f32 acc) -----------------------
// CTA = 128 threads (4 warps, 2m x 2n), CTA tile 128x128, warp tile 64x64.
// 2 CTAs/SM restore bubble-hiding; 128 B/MMA keeps crossbar off critical path.
__global__ __launch_bounds__(128, 2)
void gemm_f16(const float* __restrict__ bias, float* __restrict__ out) {
    extern __shared__ char smem[];
    __shared__ float bias_sh[64];

    const int tid = threadIdx.x;
    const int wid = tid >> 5, lid = tid & 31;
    const int n_base = blockIdx.x * 128;
    const int m_base = blockIdx.y * 128;

    const uint32_t sb = smem_u32(smem);
    if (tid < 64) bias_sh[tid] = bias[tid];

    // warp layout: 2 (m) x 2 (n); warp tile 64 x 64
    const int wm = (wid & 1) * 64;
    const int wn = (wid >> 1) * 64;
    const int l15 = lid & 15;
    const int lhalf = lid >> 4;

    uint32_t aoff[4]; int ars[4];
#pragma unroll
    for (int mi = 0; mi < 4; mi++) {
        int ar = wm + mi * 16 + l15;
        aoff[mi] = (uint32_t)(ar * 128);
        ars[mi] = ar & 7;
    }
    uint32_t boff[4]; int brs[4];
#pragma unroll
    for (int p = 0; p < 4; p++) {
        int br = wn + p * 16 + l15;
        boff[p] = (uint32_t)(br * 128);
        brs[p] = br & 7;
    }

    float acc[4][8][4];
#pragma unroll
    for (int mi = 0; mi < 4; mi++)
#pragma unroll
        for (int ni = 0; ni < 8; ni++)
#pragma unroll
            for (int q = 0; q < 4; q++) acc[mi][ni][q] = 0.0f;

    const __half* xa = g_Xh + (size_t)m_base * KK;
    const __half* xb = g_KTh + (size_t)n_base * KK;

    load_stage(sb, 0, 0, xa, xb, tid);
    load_stage(sb, 1, 1, xa, xb, tid);

    for (int kt = 0; kt < NKT; kt++) {
        if (kt == NKT - 1) {
            asm volatile("cp.async.wait_group 0;" ::: "memory");
        } else {
            asm volatile("cp.async.wait_group 1;" ::: "memory");
        }
        __syncthreads();
        if (kt + 2 < NKT) {
            int slot = kt + 2;
            slot = slot - (slot / STAGES) * STAGES;
            load_stage(sb, slot, kt + 2, xa, xb, tid);
        }
        {
            int cs = kt - (kt / STAGES) * STAGES;
            const uint32_t baseA = sb + (uint32_t)cs * STAGE_BYTES;
            const uint32_t baseB = baseA + (uint32_t)A_BYTES;
#pragma unroll
            for (int ks = 0; ks < 4; ks++) {          // 4 x k16 per BK=64
                uint32_t a[4][4], b[4][4];
                const int ch = ks * 2 + lhalf;        // 16B chunk within row
#pragma unroll
                for (int mi = 0; mi < 4; mi++)
                    LDSM4(a[mi], baseA + aoff[mi] + (uint32_t)((ch ^ ars[mi]) << 4));
#pragma unroll
                for (int p = 0; p < 4; p++)
                    LDSM4(b[p], baseB + boff[p] + (uint32_t)((ch ^ brs[p]) << 4));
#pragma unroll
                for (int mi = 0; mi < 4; mi++) {
#pragma unroll
                    for (int ni = 0; ni < 8; ni++) {
                        const int p = ni >> 1, t = ni & 1;
                        MMA_F16(acc[mi][ni], a[mi], b[p][t], b[p][t + 2]);
                    }
                }
            }
        }
    }

    // epilogue: coalesced float2 stores + bias
    const int r4 = lid >> 2;
    const int c2 = (lid & 3) * 2;
    float* obase = out + (size_t)m_base * NNDIM + n_base;
#pragma unroll
    for (int mi = 0; mi < 4; mi++) {
#pragma unroll
        for (int ni = 0; ni < 8; ni++) {
            const int row = wm + mi * 16 + r4;
            const int col = wn + ni * 8 + c2;
            const float bx = bias_sh[col & 63];
            const float by = bias_sh[(col + 1) & 63];
            float2 v0, v1;
            v0.x = acc[mi][ni][0] + bx;
            v0.y = acc[mi][ni][1] + by;
            v1.x = acc[mi][ni][2] + bx;
            v1.y = acc[mi][ni][3] + by;
            *reinterpret_cast<float2*>(obase + (size_t)row * NNDIM + col) = v0;
            *reinterpret_cast<float2*>(obase + (size_t)(row + 8) * NNDIM + col) = v1;
        }
    }
}

// ---------------- launch ----------------
extern "C" void kernel_launch(void* const* d_in, const int* in_sizes, int n_in,
                              void* d_out, int out_size) {
    const float* x = nullptr;
    const float* w = nullptr;
    const float* bias = nullptr;
    const void* po = nullptr;
    for (int t = 0; t < n_in; t++) {
        switch (in_sizes[t]) {
            case BATCH * PP * CIN:   x    = (const float*)d_in[t]; break;
            case COUT * CIN * NORB:  w    = (const float*)d_in[t]; break;
            case COUT:               bias = (const float*)d_in[t]; break;
            case PP * PP:            po   = d_in[t];               break;
            default: break;
        }
    }
    float* out = (float*)d_out;

    build_kt<<<(NNDIM * KK / 8) / 256, 256>>>(w, po);
    convert_x<<<(int)(((size_t)BATCH * KK / 8) / 256), 256>>>(x);

    cudaFuncSetAttribute(gemm_f16, cudaFuncAttributeMaxDynamicSharedMemorySize, SMEM_DYN);
    gemm_f16<<<dim3(NNDIM / 128, BATCH / 128), 128, SMEM_DYN>>>(bias, out);
}

// round 11
// speedup vs baseline: 1.6470x; 1.5047x over previous
#include <cuda_runtime.h>
#include <cuda_fp16.h>
#include <cstdint>
#include <cstddef>

// Problem constants
#define BATCH   32768
#define PP      24
#define CIN     64
#define COUT    64
#define NORB    24
#define KK      1536          // P*CIN  (GEMM K)
#define NNDIM   1536          // P*COUT (GEMM N)
#define BK      64            // halfs per k-tile (128 B rows)
#define NKT     (KK / BK)     // 24
#define STAGES  3
#define STAGE_BYTES 32768     // A 16KB + B 16KB
#define SMEM_DYN (STAGES * STAGE_BYTES)

// grid split for merged prep kernel
#define KT_BLOCKS   ((NNDIM * KK / 8) / 256)                    // 1152
#define CVT_BLOCKS  ((int)(((size_t)BATCH * KK / 8) / 256))     // 24576

// fp16 operands (device-global scratch; no allocations allowed)
__device__ __half g_Xh[(size_t)BATCH * KK];          // x in fp16, row-major [m][k]
__device__ __half g_KTh[(size_t)NNDIM * KK];         // gathered kernel, [n][k]

// ---------------- helpers ----------------
__device__ __forceinline__ uint32_t smem_u32(const void* p) {
    uint32_t a;
    asm("{ .reg .u64 t; cvta.to.shared.u64 t, %1; cvt.u32.u64 %0, t; }"
        : "=r"(a) : "l"(p));
    return a;
}

#define LDSM4(r, addr) \
    asm volatile("ldmatrix.sync.aligned.m8n8.x4.shared.b16 {%0,%1,%2,%3}, [%4];" \
                 : "=r"((r)[0]), "=r"((r)[1]), "=r"((r)[2]), "=r"((r)[3]) \
                 : "r"(addr))

#define MMA_F16(c, a, b0, b1) \
    asm volatile("mma.sync.aligned.m16n8k16.row.col.f32.f16.f16.f32 " \
                 "{%0,%1,%2,%3}, {%4,%5,%6,%7}, {%8,%9}, {%0,%1,%2,%3};" \
                 : "+f"((c)[0]), "+f"((c)[1]), "+f"((c)[2]), "+f"((c)[3]) \
                 : "r"((a)[0]), "r"((a)[1]), "r"((a)[2]), "r"((a)[3]), \
                   "r"(b0), "r"(b1))

// ---------------- kernel 1: merged prep (KT gather + x convert) ----------------
// Blocks [0, KT_BLOCKS): gather KT -> fp16 (with inline pair_orbit dtype detect).
// Blocks [KT_BLOCKS, KT_BLOCKS+CVT_BLOCKS): convert x -> fp16.
__global__ __launch_bounds__(256) void prep(const float* __restrict__ w,
                                            const void* __restrict__ po,
                                            const float* __restrict__ x) {
    if (blockIdx.x >= KT_BLOCKS) {
        // ---- convert x -> fp16 ----
        size_t idx = (size_t)(blockIdx.x - KT_BLOCKS) * 256 + threadIdx.x;
        const float4 f0 = *reinterpret_cast<const float4*>(x + idx * 8);
        const float4 f1 = *reinterpret_cast<const float4*>(x + idx * 8 + 4);
        __half2 h[4];
        h[0] = __floats2half2_rn(f0.x, f0.y);
        h[1] = __floats2half2_rn(f0.z, f0.w);
        h[2] = __floats2half2_rn(f1.x, f1.y);
        h[3] = __floats2half2_rn(f1.z, f1.w);
        *reinterpret_cast<uint4*>(&g_Xh[idx * 8]) = *reinterpret_cast<uint4*>(h);
        return;
    }
    // ---- gather KT ----
    // pair_orbit dtype ambiguity (int32 vs int64): if int64 with values < 24,
    // every odd 32-bit word is 0; 288 random int32 values in [0,24) are
    // ~never all zero in those positions.
    __shared__ int is64_sh;
    {
        const uint32_t* pr = (const uint32_t*)po;
        if (threadIdx.x == 0) is64_sh = 1;
        __syncthreads();
        int t = threadIdx.x;
        if (t < 288 && pr[2 * t + 1] != 0u) atomicAnd(&is64_sh, 0);
        __syncthreads();
    }
    const int is64 = is64_sh;

    int idx = blockIdx.x * 256 + threadIdx.x;          // 0 .. NN*KK/8-1
    int n = idx / (KK / 8);
    int k0 = (idx - n * (KK / 8)) * 8;
    int i = n >> 6, o = n & 63;
    int j = k0 >> 6;
    int c0 = k0 & 63;
    int orb;
    if (is64) orb = (int)((const long long*)po)[i * PP + j];
    else      orb = ((const int*)po)[i * PP + j];
    orb = (orb < 0) ? 0 : (orb >= NORB ? NORB - 1 : orb);
    const float* wp = w + o * (CIN * NORB) + c0 * NORB + orb;
    __half2 h[4];
#pragma unroll
    for (int q = 0; q < 4; q++)
        h[q] = __floats2half2_rn(wp[(2 * q) * NORB], wp[(2 * q + 1) * NORB]);
    *reinterpret_cast<uint4*>(&g_KTh[(size_t)n * KK + k0]) =
        *reinterpret_cast<uint4*>(h);
}

// ---------------- stage loader (256 threads) ----------------
// A tile: 128 rows x 64 halfs (128B rows), swizzle (16B chunk ch ^= row&7)
// B tile: same shape at +16KB
__device__ __forceinline__ void load_stage(uint32_t sb, int slot, int kt,
                                           const __half* __restrict__ xa,
                                           const __half* __restrict__ xb, int tid) {
    const uint32_t base = sb + (uint32_t)slot * STAGE_BYTES;
    const __half* xs = xa + kt * BK;
    const __half* bs = xb + kt * BK;
#pragma unroll
    for (int it = 0; it < 4; it++) {
        int idx = tid + it * 256;                 // 0..1023
        int row = idx >> 3, ch = idx & 7;
        uint32_t dst = base + (uint32_t)(row * 128) + (uint32_t)((ch ^ (row & 7)) << 4);
        const __half* src = xs + (size_t)row * KK + ch * 8;
        asm volatile("cp.async.cg.shared.global [%0], [%1], 16;" :: "r"(dst), "l"(src));
    }
#pragma unroll
    for (int it = 0; it < 4; it++) {
        int idx = tid + it * 256;
        int row = idx >> 3, ch = idx & 7;
        uint32_t dst = base + 16384u + (uint32_t)(row * 128) + (uint32_t)((ch ^ (row & 7)) << 4);
        const __half* src = bs + (size_t)row * KK + ch * 8;
        asm volatile("cp.async.cg.shared.global [%0], [%1], 16;" :: "r"(dst), "l"(src));
    }
    asm volatile("cp.async.commit_group;" ::: "memory");
}

// ---------------- kernel 2: fp16 mma.sync GEMM (f32 acc) — R5 config ----------
// out[m, n] = sum_k Xh[m,k] * KTh[n,k] + bias[n % 64]
// CTA 256 thr (8 warps, 2m x 4n), CTA tile 128x128, warp tile 64x32, 2 CTAs/SM.
__global__ __launch_bounds__(256, 2)
void gemm_f16(const float* __restrict__ bias, float* __restrict__ out) {
    extern __shared__ char smem[];
    __shared__ float bias_sh[64];

    const int tid = threadIdx.x;
    const int wid = tid >> 5, lid = tid & 31;
    const int n_base = blockIdx.x * 128;
    const int m_base = blockIdx.y * 128;

    const uint32_t sb = smem_u32(smem);
    if (tid < 64) bias_sh[tid] = bias[tid];

    // warp layout: 2 (m) x 4 (n); warp tile 64 x 32
    const int wm = (wid & 1) * 64;
    const int wn = (wid >> 1) * 32;
    const int l15 = lid & 15;
    const int lhalf = lid >> 4;

    uint32_t aoff[4]; int ars[4];
#pragma unroll
    for (int mi = 0; mi < 4; mi++) {
        int ar = wm + mi * 16 + l15;
        aoff[mi] = (uint32_t)(ar * 128);
        ars[mi] = ar & 7;
    }
    uint32_t boff[2]; int brs[2];
#pragma unroll
    for (int p = 0; p < 2; p++) {
        int br = wn + p * 16 + l15;
        boff[p] = (uint32_t)(br * 128);
        brs[p] = br & 7;
    }

    float acc[4][4][4];
#pragma unroll
    for (int mi = 0; mi < 4; mi++)
#pragma unroll
        for (int ni = 0; ni < 4; ni++)
#pragma unroll
            for (int q = 0; q < 4; q++) acc[mi][ni][q] = 0.0f;

    const __half* xa = g_Xh + (size_t)m_base * KK;
    const __half* xb = g_KTh + (size_t)n_base * KK;

    load_stage(sb, 0, 0, xa, xb, tid);
    load_stage(sb, 1, 1, xa, xb, tid);

    for (int kt = 0; kt < NKT; kt++) {
        if (kt == NKT - 1) {
            asm volatile("cp.async.wait_group 0;" ::: "memory");
        } else {
            asm volatile("cp.async.wait_group 1;" ::: "memory");
        }
        __syncthreads();
        if (kt + 2 < NKT) {
            int slot = kt + 2;
            slot = slot - (slot / STAGES) * STAGES;
            load_stage(sb, slot, kt + 2, xa, xb, tid);
        }
        {
            int cs = kt - (kt / STAGES) * STAGES;
            const uint32_t baseA = sb + (uint32_t)cs * STAGE_BYTES;
            const uint32_t baseB = baseA + 16384u;
#pragma unroll
            for (int ks = 0; ks < 4; ks++) {          // 4 x k16 per BK=64
                uint32_t a[4][4], b[2][4];
                const int ch = ks * 2 + lhalf;        // 16B chunk within row
#pragma unroll
                for (int mi = 0; mi < 4; mi++)
                    LDSM4(a[mi], baseA + aoff[mi] + (uint32_t)((ch ^ ars[mi]) << 4));
#pragma unroll
                for (int p = 0; p < 2; p++)
                    LDSM4(b[p], baseB + boff[p] + (uint32_t)((ch ^ brs[p]) << 4));
#pragma unroll
                for (int mi = 0; mi < 4; mi++) {
#pragma unroll
                    for (int ni = 0; ni < 4; ni++) {
                        const int p = ni >> 1, t = ni & 1;
                        MMA_F16(acc[mi][ni], a[mi], b[p][t], b[p][t + 2]);
                    }
                }
            }
        }
    }

    // epilogue: coalesced float2 stores + bias
    const int r4 = lid >> 2;
    const int c2 = (lid & 3) * 2;
    float* obase = out + (size_t)m_base * NNDIM + n_base;
#pragma unroll
    for (int mi = 0; mi < 4; mi++) {
#pragma unroll
        for (int ni = 0; ni < 4; ni++) {
            const int row = wm + mi * 16 + r4;
            const int col = wn + ni * 8 + c2;
            const float bx = bias_sh[col & 63];
            const float by = bias_sh[(col + 1) & 63];
            float2 v0, v1;
            v0.x = acc[mi][ni][0] + bx;
            v0.y = acc[mi][ni][1] + by;
            v1.x = acc[mi][ni][2] + bx;
            v1.y = acc[mi][ni][3] + by;
            *reinterpret_cast<float2*>(obase + (size_t)row * NNDIM + col) = v0;
            *reinterpret_cast<float2*>(obase + (size_t)(row + 8) * NNDIM + col) = v1;
        }
    }
}

// ---------------- launch ----------------
extern "C" void kernel_launch(void* const* d_in, const int* in_sizes, int n_in,
                              void* d_out, int out_size) {
    const float* x = nullptr;
    const float* w = nullptr;
    const float* bias = nullptr;
    const void* po = nullptr;
    for (int t = 0; t < n_in; t++) {
        switch (in_sizes[t]) {
            case BATCH * PP * CIN:   x    = (const float*)d_in[t]; break;
            case COUT * CIN * NORB:  w    = (const float*)d_in[t]; break;
            case COUT:               bias = (const float*)d_in[t]; break;
            case PP * PP:            po   = d_in[t];               break;
            default: break;
        }
    }
    float* out = (float*)d_out;

    // 2 launches per call: [prep, gemm]  (aligns ncu -s 5 window onto gemm)
    prep<<<KT_BLOCKS + CVT_BLOCKS, 256>>>(w, po, x);

    cudaFuncSetAttribute(gemm_f16, cudaFuncAttributeMaxDynamicSharedMemorySize, SMEM_DYN);
    gemm_f16<<<dim3(NNDIM / 128, BATCH / 128), 256, SMEM_DYN>>>(bias, out);
}